// round 4
// baseline (speedup 1.0000x reference)
#include <cuda_runtime.h>

// CenterLoss: mean_i ||x_i - centers[labels_i]||^2
//   = mean( ||x||^2 + ||c||^2 - 2 x.c )
// x: [4096, 512] f32, centers: [7001, 512] f32, labels: [4096] i32 -> out: [1] f32

#define BATCH 4096
#define DIM 512
#define VEC (DIM / 4)     // 128 float4 per row
#define NBLK 512
#define BLOCK 256
#define SPB 8             // samples per block (4 per 128-thread half)
#define NSLOT 64

// 64 accumulation slots, 128B apart (avoid same-address atomic serialization
// and LTS hash pair-collisions).
__device__ float g_slots[NSLOT * 32];
__device__ unsigned int g_count = 0;

__global__ __launch_bounds__(BLOCK, 4)
void center_loss_kernel(const float4* __restrict__ x,
                        const float4* __restrict__ c,
                        const int4* __restrict__ labels4,
                        float* __restrict__ out)
{
    const int t = threadIdx.x;        // 0..255
    const int b = blockIdx.x;
    const int h = t >> 7;             // half 0/1 -> samples [4h, 4h+4)
    const int lane128 = t & 127;      // float4 lane within a row
    const int base = b * SPB + h * 4;

    // One int4 per half fetches its 4 labels (broadcast load).
    const int4 lv = __ldg(&labels4[b * 2 + h]);
    const int labs[4] = { lv.x, lv.y, lv.z, lv.w };

    // Decomposed accumulation: each loaded float4 consumed independently.
    float axx = 0.0f, acc_ = 0.0f, axc = 0.0f;
#pragma unroll
    for (int s = 0; s < 4; s++) {
        float4 xv = x[(base + s) * VEC + lane128];
        axx = fmaf(xv.x, xv.x, axx);
        axx = fmaf(xv.y, xv.y, axx);
        axx = fmaf(xv.z, xv.z, axx);
        axx = fmaf(xv.w, xv.w, axx);
        float4 cv = c[labs[s] * VEC + lane128];
        acc_ = fmaf(cv.x, cv.x, acc_);
        acc_ = fmaf(cv.y, cv.y, acc_);
        acc_ = fmaf(cv.z, cv.z, acc_);
        acc_ = fmaf(cv.w, cv.w, acc_);
        axc = fmaf(xv.x, cv.x, axc);
        axc = fmaf(xv.y, cv.y, axc);
        axc = fmaf(xv.z, cv.z, axc);
        axc = fmaf(xv.w, cv.w, axc);
    }
    float acc = axx + acc_ - 2.0f * axc;

    // Warp reduce
#pragma unroll
    for (int o = 16; o; o >>= 1) acc += __shfl_xor_sync(0xffffffffu, acc, o);

    __shared__ float ws[BLOCK / 32];
    if ((t & 31) == 0) ws[t >> 5] = acc;
    __syncthreads();

    // Warp 0 finishes the CTA and handles the global reduction.
    if (t < 32) {
        unsigned int v = 0;
        if (t == 0) {
            float p = 0.0f;
#pragma unroll
            for (int w = 0; w < BLOCK / 32; w++) p += ws[w];
            // Relaxed RED to a spread slot (posted, no return).
            atomicAdd(&g_slots[(b & (NSLOT - 1)) * 32], p);
            // Ticket with acq_rel: release orders the RED above before the
            // ticket; acquire orders the final slot reads after it.
            asm volatile("atom.add.acq_rel.gpu.global.u32 %0, [%1], 1;"
                         : "=r"(v) : "l"(&g_count) : "memory");
        }
        v = __shfl_sync(0xffffffffu, v, 0);
        if (v == NBLK - 1) {          // last CTA: all REDs are visible
            float s0, s1;
            asm volatile("ld.global.cg.f32 %0, [%1];"
                         : "=f"(s0) : "l"(&g_slots[t * 32]) : "memory");
            asm volatile("ld.global.cg.f32 %0, [%1];"
                         : "=f"(s1) : "l"(&g_slots[(t + 32) * 32]) : "memory");
            float vsum = s0 + s1;
#pragma unroll
            for (int o = 16; o; o >>= 1) vsum += __shfl_xor_sync(0xffffffffu, vsum, o);
            if (t == 0) out[0] = vsum * (1.0f / (float)BATCH);
            // Self-reset for the next graph replay (ordered by kernel end).
            g_slots[t * 32] = 0.0f;
            g_slots[(t + 32) * 32] = 0.0f;
            if (t == 0) g_count = 0u;
        }
    }
}

extern "C" void kernel_launch(void* const* d_in, const int* in_sizes, int n_in,
                              void* d_out, int out_size)
{
    const float4* x = (const float4*)d_in[0];
    const float4* c = (const float4*)d_in[1];
    const int4* labels4 = (const int4*)d_in[2];
    float* out = (float*)d_out;
    center_loss_kernel<<<NBLK, BLOCK>>>(x, c, labels4, out);
}

// round 5
// speedup vs baseline: 1.0257x; 1.0257x over previous
#include <cuda_runtime.h>

// CenterLoss: mean_i ||x_i - centers[labels_i]||^2
//   = mean( ||x||^2 + ||c||^2 - 2 x.c )
// x: [4096, 512] f32, centers: [7001, 512] f32, labels: [4096] i32 -> out: [1] f32

#define BATCH 4096
#define DIM 512
#define VEC (DIM / 4)     // 128 float4 per row
#define NBLK 148          // exactly 1 CTA per SM: zero placement imbalance
#define BLOCK 512         // 4 groups of 128 threads
#define REM (BATCH - NBLK * 27)   // 100: CTAs [0,100) handle 28 samples, rest 27

__device__ float g_slots[NBLK * 32];  // one slot per CTA, 128B apart
__device__ unsigned int g_count = 0;

__global__ __launch_bounds__(BLOCK, 1)
void center_loss_kernel(const float4* __restrict__ x,
                        const float4* __restrict__ c,
                        const int* __restrict__ labels,
                        float* __restrict__ out)
{
    const int t = threadIdx.x;        // 0..511
    const int b = blockIdx.x;
    const int g = t >> 7;             // group 0..3
    const int lane128 = t & 127;      // float4 lane within a row

    // Contiguous sample range for this CTA: start..start+cnt
    const int start = b * 27 + (b < REM ? b : REM);
    const int cnt = (b < REM) ? 28 : 27;

    // Group g handles samples start + g + 4*i, i = 0..6 (i=6 conditional).
    // Front-load the (up to) 7 labels: independent scalar LDGs.
    const bool has7 = (g + 24) < cnt;
    int labs[7];
#pragma unroll
    for (int i = 0; i < 6; i++) labs[i] = __ldg(&labels[start + g + 4 * i]);
    labs[6] = has7 ? __ldg(&labels[start + g + 24]) : 0;

    // Decomposed accumulation: every loaded float4 consumed independently.
    float axx = 0.0f, acc_ = 0.0f, axc = 0.0f;
#pragma unroll
    for (int i = 0; i < 6; i++) {
        const int s = start + g + 4 * i;
        float4 xv = x[s * VEC + lane128];
        axx = fmaf(xv.x, xv.x, axx);
        axx = fmaf(xv.y, xv.y, axx);
        axx = fmaf(xv.z, xv.z, axx);
        axx = fmaf(xv.w, xv.w, axx);
        float4 cv = c[labs[i] * VEC + lane128];
        acc_ = fmaf(cv.x, cv.x, acc_);
        acc_ = fmaf(cv.y, cv.y, acc_);
        acc_ = fmaf(cv.z, cv.z, acc_);
        acc_ = fmaf(cv.w, cv.w, acc_);
        axc = fmaf(xv.x, cv.x, axc);
        axc = fmaf(xv.y, cv.y, axc);
        axc = fmaf(xv.z, cv.z, axc);
        axc = fmaf(xv.w, cv.w, axc);
    }
    if (has7) {
        const int s = start + g + 24;
        float4 xv = x[s * VEC + lane128];
        float4 cv = c[labs[6] * VEC + lane128];
        axx = fmaf(xv.x, xv.x, axx);
        axx = fmaf(xv.y, xv.y, axx);
        axx = fmaf(xv.z, xv.z, axx);
        axx = fmaf(xv.w, xv.w, axx);
        acc_ = fmaf(cv.x, cv.x, acc_);
        acc_ = fmaf(cv.y, cv.y, acc_);
        acc_ = fmaf(cv.z, cv.z, acc_);
        acc_ = fmaf(cv.w, cv.w, acc_);
        axc = fmaf(xv.x, cv.x, axc);
        axc = fmaf(xv.y, cv.y, axc);
        axc = fmaf(xv.z, cv.z, axc);
        axc = fmaf(xv.w, cv.w, axc);
    }
    float acc = axx + acc_ - 2.0f * axc;

    // Warp reduce
#pragma unroll
    for (int o = 16; o; o >>= 1) acc += __shfl_xor_sync(0xffffffffu, acc, o);

    __shared__ float ws[BLOCK / 32];   // 16 warp sums
    if ((t & 31) == 0) ws[t >> 5] = acc;
    __syncthreads();

    // Warp 0: CTA sum -> plain STG to private slot; acq_rel ticket orders it.
    if (t < 32) {
        unsigned int v = 0;
        if (t == 0) {
            float p = 0.0f;
#pragma unroll
            for (int w = 0; w < BLOCK / 32; w++) p += ws[w];
            g_slots[b * 32] = p;   // private slot: plain store, no atomic
            asm volatile("atom.add.acq_rel.gpu.global.u32 %0, [%1], 1;"
                         : "=r"(v) : "l"(&g_count) : "memory");
        }
        v = __shfl_sync(0xffffffffu, v, 0);
        if (v == NBLK - 1) {       // last CTA: all slot stores are visible
            float vsum = 0.0f;
#pragma unroll
            for (int k = 0; k < 5; k++) {
                int idx = t + k * 32;
                if (idx < NBLK) {
                    float s;
                    asm volatile("ld.global.cg.f32 %0, [%1];"
                                 : "=f"(s) : "l"(&g_slots[idx * 32]) : "memory");
                    vsum += s;
                }
            }
#pragma unroll
            for (int o = 16; o; o >>= 1) vsum += __shfl_xor_sync(0xffffffffu, vsum, o);
            if (t == 0) {
                out[0] = vsum * (1.0f / (float)BATCH);
                g_count = 0u;      // self-reset for next graph replay
            }
        }
    }
}

extern "C" void kernel_launch(void* const* d_in, const int* in_sizes, int n_in,
                              void* d_out, int out_size)
{
    const float4* x = (const float4*)d_in[0];
    const float4* c = (const float4*)d_in[1];
    const int* labels = (const int*)d_in[2];
    float* out = (float*)d_out;
    center_loss_kernel<<<NBLK, BLOCK>>>(x, c, labels, out);
}